// round 12
// baseline (speedup 1.0000x reference)
#include <cuda_runtime.h>
#include <cuda_fp16.h>
#include <math.h>
#include <stdint.h>

#define NB 16
#define NS 2048
#define NH 128
#define ND 64
#define CB 8          // batches per chunk (E kept L2-resident per chunk)

typedef unsigned long long u64;

// ---------------- scratch (device globals; no allocation allowed) ----------------
__device__ float g_pe[NS * NH];
__device__ __half g_Qh[NB * NS * ND];           // fp16 Q, PRE-SCALED by log2(e)/8
__device__ __half g_Kh[NB * NS * ND];           // fp16 K
__device__ float g_wvf[NH];
__device__ float g_u[NB * NS];
__device__ float g_Z[NB * NS];
__device__ float g_w[NB * NS];
// E chunk in FRAGMENT-BLOCKED layout (written by k_scores, read only by k_out):
// uint2 index = ((((zb*16+qt)*16+kt)*8 + warp)*16 + mi*8+j)*32 + lane
// value = (half2(rowA c,c+1), half2(rowB c,c+1)), rowB = rowA+8. E = 2^(s*log2e/8).
__device__ __half g_E[(size_t)CB * NS * NS];    // 67 MB (L2-resident, reused)

// ---------------- helpers ---------------------------------------------------------
__device__ __forceinline__ uint32_t smem_u32(const void* p) {
    uint32_t a;
    asm("{ .reg .u64 t; cvta.to.shared.u64 t, %1; cvt.u32.u64 %0, t; }" : "=r"(a) : "l"(p));
    return a;
}
__device__ __forceinline__ void ldm_x4(uint32_t* r, uint32_t addr) {
    asm volatile("ldmatrix.sync.aligned.m8n8.x4.shared.b16 {%0,%1,%2,%3}, [%4];"
                 : "=r"(r[0]), "=r"(r[1]), "=r"(r[2]), "=r"(r[3]) : "r"(addr));
}
__device__ __forceinline__ void mma_f16(float* c, const uint32_t* a,
                                        uint32_t b0, uint32_t b1) {
    asm volatile(
        "mma.sync.aligned.m16n8k16.row.col.f32.f16.f16.f32 "
        "{%0,%1,%2,%3}, {%4,%5,%6,%7}, {%8,%9}, {%0,%1,%2,%3};"
        : "+f"(c[0]), "+f"(c[1]), "+f"(c[2]), "+f"(c[3])
        : "r"(a[0]), "r"(a[1]), "r"(a[2]), "r"(a[3]), "r"(b0), "r"(b1));
}
__device__ __forceinline__ uint32_t ex2_h2(uint32_t s) {
    uint32_t r; asm("ex2.approx.f16x2 %0, %1;" : "=r"(r) : "r"(s)); return r;
}
__device__ __forceinline__ u64 pack2(float lo, float hi) {
    u64 r; asm("mov.b64 %0, {%1,%2};" : "=l"(r) : "f"(lo), "f"(hi)); return r;
}
__device__ __forceinline__ void fma2(u64& c, u64 a, u64 b) {
    asm("fma.rn.f32x2 %0, %1, %2, %0;" : "+l"(c) : "l"(a), "l"(b));
}
__device__ __forceinline__ float2 unpack2(u64 v) {
    float lo, hi; asm("mov.b64 {%0,%1}, %2;" : "=f"(lo), "=f"(hi) : "l"(v));
    return make_float2(lo, hi);
}

// ---------------- kernel 1: sinusoidal PE -----------------------------------------
__global__ void k_pe() {
    int t = threadIdx.x;
    int p = blockIdx.x * 4 + (t >> 6);
    int i = t & 63;
    double inv_rate = exp2(-(double)i * 0.20762050593046016);  // 10000^(-i/64)
    double ang = (double)p * inv_rate;
    double k = rint(ang * 0.15915494309189535);
    double r = fma(-k, 6.283185307179586, ang);
    r = fma(-k, 2.4492935982947064e-16, r);
    float s, c;
    sincosf((float)r, &s, &c);
    g_pe[p * NH + 2 * i]     = s;
    g_pe[p * NH + 2 * i + 1] = c;
}

// ---------------- kernel 2: wvf = Wv @ Wf -----------------------------------------
__global__ void k_wvf(const float* __restrict__ Wv, const float* __restrict__ Wf) {
    int h = threadIdx.x;
    float s = 0.f;
    #pragma unroll 8
    for (int d = 0; d < ND; d++) s += Wv[h * ND + d] * Wf[d];
    g_wvf[h] = s;
}

// ---------------- kernel 3: fused xp=x+pe -> {Q*C, K} fp16 (HMMA) + u + Z=0 -------
__global__ __launch_bounds__(512, 2) void k_qk(const float* __restrict__ x,
                                               const float* __restrict__ Wq,
                                               const float* __restrict__ Wk) {
    extern __shared__ __align__(16) char qs[];
    char* XPs = qs;             // [128 rows][256 B]
    char* Ws  = qs + 32768;     // [128 n][256 B]
    int t = threadIdx.x;
    int w = t >> 5, lane = t & 31;
    int r0 = blockIdx.x * 128;
    int s0 = r0 & (NS - 1);

    int zi = blockIdx.x * 512 + t;          // zero Z, bounds-guarded
    if (zi < NB * NS) g_Z[zi] = 0.f;

    // stage W transposed to [n][k] fp16
    #pragma unroll
    for (int i = 0; i < 4; i++) {
        int id = t + i * 512;
        int n = id & 127, o = id >> 7;
        const float* src = (n < 64) ? (Wq + n) : (Wk + (n - 64));
        float v0 = src[(8 * o + 0) * 64], v1 = src[(8 * o + 1) * 64];
        float v2 = src[(8 * o + 2) * 64], v3 = src[(8 * o + 3) * 64];
        float v4 = src[(8 * o + 4) * 64], v5 = src[(8 * o + 5) * 64];
        float v6 = src[(8 * o + 6) * 64], v7 = src[(8 * o + 7) * 64];
        __half2 h0 = __floats2half2_rn(v0, v1);
        __half2 h1 = __floats2half2_rn(v2, v3);
        __half2 h2 = __floats2half2_rn(v4, v5);
        __half2 h3 = __floats2half2_rn(v6, v7);
        int chunk = o ^ (n & 7);
        *(uint4*)(Ws + n * 256 + chunk * 16) =
            make_uint4(*(uint32_t*)&h0, *(uint32_t*)&h1, *(uint32_t*)&h2, *(uint32_t*)&h3);
    }

    // stage XP (fp16) + u (fp32)
    float4 wv = ((const float4*)g_wvf)[lane];
    #pragma unroll
    for (int i = 0; i < 8; i++) {
        int row = w + 16 * i;
        float4 xv = ((const float4*)(x    + (size_t)(r0 + row) * NH))[lane];
        float4 pv = ((const float4*)(g_pe + (size_t)(s0 + row) * NH))[lane];
        float xpx = xv.x + pv.x, xpy = xv.y + pv.y;
        float xpz = xv.z + pv.z, xpw = xv.w + pv.w;
        float up = xpx * wv.x + xpy * wv.y + xpz * wv.z + xpw * wv.w;
        #pragma unroll
        for (int off = 16; off; off >>= 1) up += __shfl_down_sync(0xffffffffu, up, off);
        if (lane == 0) g_u[r0 + row] = up;
        __half2 hA = __floats2half2_rn(xpx, xpy);
        __half2 hB = __floats2half2_rn(xpz, xpw);
        int chunk = (lane >> 1) ^ (row & 7);
        *(uint2*)(XPs + row * 256 + chunk * 16 + (lane & 1) * 8) =
            make_uint2(*(uint32_t*)&hA, *(uint32_t*)&hB);
    }
    __syncthreads();

    // mma: 16 warps = 8 warp_m x 2 warp_n; warp tile 16 rows x 64 cols
    int warp_m = w >> 1, warp_n = w & 1;
    int m0 = warp_m * 16, nb0 = warp_n * 64;
    int lr = lane & 15, lch = lane >> 4;

    uint32_t aXP = smem_u32(XPs), aW = smem_u32(Ws);
    float acc[8][4] = {};
    #pragma unroll
    for (int ks = 0; ks < 8; ks++) {
        uint32_t a[4];
        int rowA = m0 + lr;
        ldm_x4(a, aXP + rowA * 256 + (((2 * ks + lch) ^ (rowA & 7)) << 4));
        #pragma unroll
        for (int nb = 0; nb < 4; nb++) {
            int rowB = nb0 + nb * 16 + lr;
            uint32_t bk[4];
            ldm_x4(bk, aW + rowB * 256 + (((2 * ks + lch) ^ (rowB & 7)) << 4));
            mma_f16(acc[2 * nb],     a, bk[0], bk[2]);
            mma_f16(acc[2 * nb + 1], a, bk[1], bk[3]);
        }
    }

    // Q gets pre-scaled by C = log2(e)/8 so k_scores' MMA emits log2(E) directly
    float scale = warp_n ? 1.0f : 0.18033688011112042f;
    int g = lane >> 2, tq = lane & 3;
    __half* base = warp_n ? g_Kh : g_Qh;
    #pragma unroll
    for (int mi = 0; mi < 2; mi++) {
        __half* drow = base + (size_t)(r0 + m0 + 8 * mi + g) * ND;
        #pragma unroll
        for (int nb = 0; nb < 4; nb++) {
            #pragma unroll
            for (int jj = 0; jj < 2; jj++) {
                int col = nb * 16 + jj * 8 + 2 * tq;
                __half2 hv = __floats2half2_rn(acc[2 * nb + jj][2 * mi] * scale,
                                               acc[2 * nb + jj][2 * mi + 1] * scale);
                *(uint32_t*)(drow + col) = *(uint32_t*)&hv;
            }
        }
    }
}

// ---------------- kernel 4: E = 2^(QK^T scaled) -> fragment-blocked gmem ----------
// MMA emits s' = log2(E) (C folded into Q). Epilogue: cvt f32x2->h2, ex2.f16x2,
// half2 csum; fragment-direct coalesced stores; Z colsum via shfl + atomics.
__global__ __launch_bounds__(256, 2) void k_scores(int b0) {
    extern __shared__ __align__(16) __half smh[];
    const int PITCH = 72;
    __half* QH = smh;                     // [128][72]
    __half* KH = smh + 128 * PITCH;

    int t = threadIdx.x;
    int w = t >> 5, lane = t & 31;
    int zb = blockIdx.z;                  // 0..CB-1 (E index)
    int b = b0 + zb;                      // global batch
    int qt = blockIdx.y;
    int kt = blockIdx.x;
    int k0 = kt * 128;

    const uint4* Qg = (const uint4*)(g_Qh + ((size_t)b * NS + qt * 128) * ND);
    const uint4* Kg = (const uint4*)(g_Kh + ((size_t)b * NS + k0) * ND);
    #pragma unroll
    for (int i = 0; i < 4; i++) {
        int e = t + i * 256;
        int r = e >> 3, c8 = e & 7;
        int off = r * PITCH + c8 * 8;
        *(uint4*)(QH + off) = Qg[e];
        *(uint4*)(KH + off) = Kg[e];
    }
    __syncthreads();

    int warp_m = w & 3, warp_n = w >> 2;
    int m0 = warp_m * 32, n0 = warp_n * 64;
    int lr = lane & 15;
    int lc = (lane >> 4) << 3;

    uint32_t aQH = smem_u32(QH), aKH = smem_u32(KH);
    float acc[2][8][4] = {};

    #pragma unroll
    for (int ks = 0; ks < 4; ks++) {
        int col = ks * 16 + lc;
        uint32_t a0[4], a1[4];
        ldm_x4(a0, aQH + ((m0 + lr) * PITCH + col) * 2);
        ldm_x4(a1, aQH + ((m0 + 16 + lr) * PITCH + col) * 2);
        #pragma unroll
        for (int nb = 0; nb < 4; nb++) {
            uint32_t bk[4];
            ldm_x4(bk, aKH + ((n0 + nb * 16 + lr) * PITCH + col) * 2);
            mma_f16(acc[0][2 * nb],     a0, bk[0], bk[2]);
            mma_f16(acc[0][2 * nb + 1], a0, bk[1], bk[3]);
            mma_f16(acc[1][2 * nb],     a1, bk[0], bk[2]);
            mma_f16(acc[1][2 * nb + 1], a1, bk[1], bk[3]);
        }
    }

    // epilogue: E = ex2(s') in half2; fragment-direct stores + half2 colsums
    uint2* Ew = (uint2*)g_E + ((((size_t)zb * 16 + qt) * 16 + kt) * 8 + w) * 512;
    __half2 ch[8];
    #pragma unroll
    for (int j = 0; j < 8; j++) ch[j] = __floats2half2_rn(0.f, 0.f);

    #pragma unroll
    for (int mi = 0; mi < 2; mi++) {
        #pragma unroll
        for (int j = 0; j < 8; j++) {
            __half2 sA = __floats2half2_rn(acc[mi][j][0], acc[mi][j][1]);  // rowA
            __half2 sB = __floats2half2_rn(acc[mi][j][2], acc[mi][j][3]);  // rowB
            uint32_t eA = ex2_h2(*(uint32_t*)&sA);
            uint32_t eB = ex2_h2(*(uint32_t*)&sB);
            Ew[(mi * 8 + j) * 32 + lane] = make_uint2(eA, eB);
            ch[j] = __hadd2(ch[j], __hadd2(*(__half2*)&eA, *(__half2*)&eB));
        }
    }

    // convert half2 partials to f32, reduce over g groups, atomics
    float csum[16];
    #pragma unroll
    for (int j = 0; j < 8; j++) {
        float2 f = __half22float2(ch[j]);
        csum[2 * j] = f.x; csum[2 * j + 1] = f.y;
    }
    #pragma unroll
    for (int off = 4; off <= 16; off <<= 1) {
        #pragma unroll
        for (int j = 0; j < 16; j++)
            csum[j] += __shfl_xor_sync(0xffffffffu, csum[j], off);
    }
    if (lane < 4) {
        int tq = lane;
        float* zp = g_Z + b * NS + k0 + n0 + 2 * tq;
        #pragma unroll
        for (int j = 0; j < 8; j++) {
            atomicAdd(zp + j * 8,     csum[2 * j]);
            atomicAdd(zp + j * 8 + 1, csum[2 * j + 1]);
        }
    }
}

// ---------------- kernel 5: w = u / Z (chunk; 16K divisions total) ----------------
__global__ void k_w(int b0) {
    int i = b0 * NS + blockIdx.x * 256 + threadIdx.x;
    g_w[i] = g_u[i] / g_Z[i];
}

// ---------------- kernel 6: out from fragment-blocked E ---------------------------
__global__ __launch_bounds__(256) void k_out(int b0, const float* __restrict__ bf,
                                             float* __restrict__ out) {
    __shared__ float ws[NS];
    int zb = blockIdx.y;
    int qt = blockIdx.x >> 2;
    int wm = blockIdx.x & 3;
    int b = b0 + zb;
    int t = threadIdx.x;

    const float4* wg = (const float4*)(g_w + b * NS);
    float4* wsm = (float4*)ws;
    #pragma unroll
    for (int i = 0; i < 2; i++) wsm[t + i * 256] = wg[t + i * 256];
    __syncthreads();

    int g = t >> 5, lane = t & 31;
    int mi = lane >> 4;
    int j = (lane >> 1) & 7;
    int tqp = lane & 1;

    int frag_off = (mi * 8 + j) * 32 + g * 4 + tqp * 2;
    const uint2* Eb = (const uint2*)g_E + (((size_t)zb * 16 + qt) * 16) * 8 * 512;

    u64 accA = 0, accB = 0;
    #pragma unroll 4
    for (int it = 0; it < 32; it++) {
        int kt = it >> 1, wn = it & 1;
        const uint4* src = (const uint4*)(Eb + ((size_t)kt * 8 + wn * 4 + wm) * 512 + frag_off);
        uint4 v = *src;
        const float4 w4 = *(const float4*)(ws + kt * 128 + wn * 64 + j * 8 + tqp * 4);
        float2 f0 = __half22float2(*(__half2*)&v.x);
        float2 f1 = __half22float2(*(__half2*)&v.y);
        float2 f2 = __half22float2(*(__half2*)&v.z);
        float2 f3 = __half22float2(*(__half2*)&v.w);
        fma2(accA, pack2(f0.x, f0.y), pack2(w4.x, w4.y));
        fma2(accA, pack2(f2.x, f2.y), pack2(w4.z, w4.w));
        fma2(accB, pack2(f1.x, f1.y), pack2(w4.x, w4.y));
        fma2(accB, pack2(f3.x, f3.y), pack2(w4.z, w4.w));
    }
    float2 pA = unpack2(accA), pB = unpack2(accB);
    float sA = pA.x + pA.y;
    float sB = pB.x + pB.y;
    #pragma unroll
    for (int off = 1; off <= 8; off <<= 1) {
        sA += __shfl_xor_sync(0xffffffffu, sA, off);
        sB += __shfl_xor_sync(0xffffffffu, sB, off);
    }
    if ((lane & 15) == 0) {
        int rA = qt * 128 + wm * 32 + mi * 16 + g;
        float bias = bf[0];
        out[b * NS + rA]     = sA + bias;
        out[b * NS + rA + 8] = sB + bias;
    }
}

// ---------------- host launcher ---------------------------------------------------
extern "C" void kernel_launch(void* const* d_in, const int* in_sizes, int n_in,
                              void* d_out, int out_size) {
    (void)in_sizes; (void)n_in; (void)out_size;
    const float* x  = (const float*)d_in[0];
    const float* Wq = (const float*)d_in[1];
    const float* Wk = (const float*)d_in[2];
    const float* Wv = (const float*)d_in[3];
    const float* Wf = (const float*)d_in[4];
    const float* bf = (const float*)d_in[5];
    float* out = (float*)d_out;

    cudaFuncSetAttribute(k_qk,     cudaFuncAttributeMaxDynamicSharedMemorySize, 65536);
    cudaFuncSetAttribute(k_scores, cudaFuncAttributeMaxDynamicSharedMemorySize, 36864);

    k_pe<<<NS / 4, 256>>>();
    k_wvf<<<1, 128>>>(Wv, Wf);
    k_qk<<<(NB * NS) / 128, 512, 65536>>>(x, Wq, Wk);

    for (int c = 0; c < NB / CB; c++) {
        int b0 = c * CB;
        dim3 sg(16, 16, CB);   // (k-tiles, q-tiles, chunk batches)
        k_scores<<<sg, 256, 36864>>>(b0);
        k_w<<<(CB * NS) / 256, 256>>>(b0);
        dim3 og(64, CB);       // (qt*4+wm, zb)
        k_out<<<og, 256>>>(b0, bf, out);
    }
}